// round 7
// baseline (speedup 1.0000x reference)
#include <cuda_runtime.h>

#define CC 192
#define HW_ 9216
#define PSTRIDE 59   // 33 softplus(mat) + 13 bias + 13 tanh(factor)

__device__ __forceinline__ float fast_sigmoid(float x) {
    float e = __expf(-x);
    return __fdividef(1.0f, 1.0f + e);
}

__device__ __forceinline__ float fast_tanh(float x) {
    float y;
    asm("tanh.approx.f32 %0, %1;" : "=f"(y) : "f"(x));
    return y;
}

__device__ __forceinline__ float softplus_fast(float x) {
    // |rel err| ~1e-6; exact passthrough for large x
    return (x > 15.0f) ? x : __logf(1.0f + __expf(x));
}

// -------------------------------------------------------------------------
// Generic slow logits (gated fallback only). Loop-based, reads params from
// shared each use -> tiny register footprint, never taxes the fast path.
// -------------------------------------------------------------------------
__device__ __noinline__ float logits_slow(const float* P, float t)
{
    float h[3];
#pragma unroll 1
    for (int i = 0; i < 3; i++) {
        float g = fmaf(P[i], t, P[33 + i]);
        h[i] = g + P[46 + i] * tanhf(g);
    }
#pragma unroll 1
    for (int l = 1; l < 4; l++) {
        const float* M = P + 3 + (l - 1) * 9;
        float g[3];
#pragma unroll 1
        for (int r = 0; r < 3; r++) {
            float s = P[33 + 3 * l + r];
#pragma unroll 1
            for (int k = 0; k < 3; k++) s = fmaf(M[3 * r + k], h[k], s);
            g[r] = s + P[46 + 3 * l + r] * tanhf(s);
        }
        h[0] = g[0]; h[1] = g[1]; h[2] = g[2];
    }
    float o = P[33 + 12];
#pragma unroll 1
    for (int k = 0; k < 3; k++) o = fmaf(P[30 + k], h[k], o);
    return o + P[46 + 12] * tanhf(o);
}

__device__ __forceinline__ float lk_from_LU(float L, float U)
{
    float su = L + U;
    float s = (su > 0.0f) ? -1.0f : ((su < 0.0f) ? 1.0f : 0.0f);  // -sign(L+U)
    float lk = fabsf(fast_sigmoid(s * U) - fast_sigmoid(s * L));
    return fmaxf(lk, 1e-9f);
}

// -------------------------------------------------------------------------
// Single fused kernel. 256 thr x 4 elems = 1024/block; 1024 | 9216 so each
// block is channel-uniform. Prologue: threads 0-58 transform the channel's
// 59 params (softplus/tanh) into shared; thread 0 composes the affine
// collapse logits(t)=a*t+b (exact when all tanh gates are zero). The input
// __ldcs loads are issued first so prologue work hides under their latency.
// Fast path per element: L = fma(a,v,b-0.5a), U = L + a.
// -------------------------------------------------------------------------
__global__ void __launch_bounds__(256, 6) eb_fused(
    const float4* __restrict__ x4, const float4* __restrict__ n4,
    float* __restrict__ out, int n4tot,
    const float* __restrict__ m0, const float* __restrict__ m1,
    const float* __restrict__ m2, const float* __restrict__ m3,
    const float* __restrict__ m4,
    const float* __restrict__ b0, const float* __restrict__ b1,
    const float* __restrict__ b2, const float* __restrict__ b3,
    const float* __restrict__ b4,
    const float* __restrict__ f0, const float* __restrict__ f1,
    const float* __restrict__ f2, const float* __restrict__ f3,
    const float* __restrict__ f4)
{
    __shared__ float  S[PSTRIDE];
    __shared__ float4 Ash;

    // Issue the streaming loads first — everything below hides under them.
    int i4 = blockIdx.x * 256 + threadIdx.x;
    float4 xv = __ldcs(x4 + i4);
    float4 nv = __ldcs(n4 + i4);

    int c = (int)((blockIdx.x * 1024u) / HW_) % CC;

    if (threadIdx.x < PSTRIDE) {
        int s = threadIdx.x;
        float val;
        if (s < 33) {
            const float* ms[5] = {m0, m1, m2, m3, m4};
            const int moff[5] = {0, 3, 12, 21, 30};
            const int msz[5]  = {3, 9, 9, 9, 3};
            int l = (s < 3) ? 0 : (s < 12) ? 1 : (s < 21) ? 2 : (s < 30) ? 3 : 4;
            val = softplus_fast(ms[l][c * msz[l] + (s - moff[l])]);
        } else if (s < 46) {
            const float* bs[5] = {b0, b1, b2, b3, b4};
            const int uoff[5] = {0, 3, 6, 9, 12};
            const int usz[5]  = {3, 3, 3, 3, 1};
            int u = s - 33;
            int l = (u < 3) ? 0 : (u < 6) ? 1 : (u < 9) ? 2 : (u < 12) ? 3 : 4;
            val = bs[l][c * usz[l] + (u - uoff[l])];
        } else {
            const float* fs[5] = {f0, f1, f2, f3, f4};
            const int uoff[5] = {0, 3, 6, 9, 12};
            const int usz[5]  = {3, 3, 3, 3, 1};
            int u = s - 46;
            int l = (u < 3) ? 0 : (u < 6) ? 1 : (u < 9) ? 2 : (u < 12) ? 3 : 4;
            val = fast_tanh(fs[l][c * usz[l] + (u - uoff[l])]);
        }
        S[s] = val;
    }
    __syncthreads();

    if (threadIdx.x == 0) {
        const float* sp = S;
        const float* bb = S + 33;
        const float* tf = S + 46;

        bool gated = false;
#pragma unroll
        for (int i = 0; i < 13; i++) gated = gated || (tf[i] != 0.0f);

        float a0 = sp[0], a1 = sp[1], a2 = sp[2];
        float v0 = bb[0], v1 = bb[1], v2 = bb[2];
#pragma unroll
        for (int l = 1; l < 4; l++) {
            const float* M = sp + 3 + (l - 1) * 9;
            const float* B = bb + 3 * l;
            float na0 = M[0]*a0 + M[1]*a1 + M[2]*a2;
            float na1 = M[3]*a0 + M[4]*a1 + M[5]*a2;
            float na2 = M[6]*a0 + M[7]*a1 + M[8]*a2;
            float nv0 = M[0]*v0 + M[1]*v1 + M[2]*v2 + B[0];
            float nv1 = M[3]*v0 + M[4]*v1 + M[5]*v2 + B[1];
            float nv2 = M[6]*v0 + M[7]*v1 + M[8]*v2 + B[2];
            a0 = na0; a1 = na1; a2 = na2;
            v0 = nv0; v1 = nv1; v2 = nv2;
        }
        float a_s = sp[30]*a0 + sp[31]*a1 + sp[32]*a2;
        float b_s = sp[30]*v0 + sp[31]*v1 + sp[32]*v2 + bb[12];
        Ash = make_float4(a_s, b_s - 0.5f * a_s, gated ? 1.0f : 0.0f, b_s);
    }
    __syncthreads();

    float4 A = Ash;
    float4 v = make_float4(xv.x + nv.x, xv.y + nv.y, xv.z + nv.z, xv.w + nv.w);

    float4* o4 = (float4*)out;
    __stcs(o4 + i4, v);  // outputs = v

    float4 lk;
    if (A.z == 0.0f) {
        float a = A.x, bm = A.y;
        float Lx = fmaf(a, v.x, bm), Ly = fmaf(a, v.y, bm);
        float Lz = fmaf(a, v.z, bm), Lw = fmaf(a, v.w, bm);
        lk.x = lk_from_LU(Lx, Lx + a);
        lk.y = lk_from_LU(Ly, Ly + a);
        lk.z = lk_from_LU(Lz, Lz + a);
        lk.w = lk_from_LU(Lw, Lw + a);
    } else {
        lk.x = lk_from_LU(logits_slow(S, v.x - 0.5f), logits_slow(S, v.x + 0.5f));
        lk.y = lk_from_LU(logits_slow(S, v.y - 0.5f), logits_slow(S, v.y + 0.5f));
        lk.z = lk_from_LU(logits_slow(S, v.z - 0.5f), logits_slow(S, v.z + 0.5f));
        lk.w = lk_from_LU(logits_slow(S, v.w - 0.5f), logits_slow(S, v.w + 0.5f));
    }
    __stcs(o4 + n4tot + i4, lk);  // likelihood
}

extern "C" void kernel_launch(void* const* d_in, const int* in_sizes, int n_in,
                              void* d_out, int out_size)
{
    const float* X  = (const float*)d_in[0];
    const float* NZ = (const float*)d_in[1];

    const float *m[5], *b[5], *f[5];
    if (in_sizes[3] == 3 * in_sizes[2]) {      // signature order
        for (int i = 0; i < 5; i++) {
            m[i] = (const float*)d_in[2 + i];
            b[i] = (const float*)d_in[7 + i];
            f[i] = (const float*)d_in[12 + i];
        }
    } else {                                   // dict order m,b,f interleaved
        for (int i = 0; i < 5; i++) {
            m[i] = (const float*)d_in[2 + 3 * i];
            b[i] = (const float*)d_in[3 + 3 * i];
            f[i] = (const float*)d_in[4 + 3 * i];
        }
    }

    int N = in_sizes[0];  // B*C*H*W = 28,311,552
    int blocks = N / 1024;  // 256 threads * 4 elems

    eb_fused<<<blocks, 256>>>(
        (const float4*)X, (const float4*)NZ, (float*)d_out, N / 4,
        m[0], m[1], m[2], m[3], m[4],
        b[0], b[1], b[2], b[3], b[4],
        f[0], f[1], f[2], f[3], f[4]);
}

// round 8
// speedup vs baseline: 1.0899x; 1.0899x over previous
#include <cuda_runtime.h>

#define CC 192
#define HW_ 9216
#define PSTRIDE 59   // 33 softplus(mat) + 13 bias + 13 tanh(factor)

__device__ float  d_param[CC * PSTRIDE];
__device__ float4 d_affine[CC];   // {a, b - 0.5a, gated_flag, b}

__device__ __forceinline__ float fast_sigmoid(float x) {
    float e = __expf(-x);
    return __fdividef(1.0f, 1.0f + e);
}

__device__ __forceinline__ float fast_tanh(float x) {
    float y;
    asm("tanh.approx.f32 %0, %1;" : "=f"(y) : "f"(x));
    return y;
}

__device__ __forceinline__ float softplus_fast(float x) {
    // |rel err| ~1e-6; exact passthrough for large x
    return (x > 15.0f) ? x : __logf(1.0f + __expf(x));
}

// -------------------------------------------------------------------------
// Prep: one WARP per channel (24 blocks x 8 warps). Slots spread across
// lanes, fast intrinsics, staged to shared; lane 0 composes the affine
// collapse logits(t) = a*t + b (exact when all tanh gates are zero).
// Signals PDL dependents after its global writes.
// -------------------------------------------------------------------------
__global__ void __launch_bounds__(256) eb_prep(
    const float* __restrict__ m0, const float* __restrict__ m1,
    const float* __restrict__ m2, const float* __restrict__ m3,
    const float* __restrict__ m4,
    const float* __restrict__ b0, const float* __restrict__ b1,
    const float* __restrict__ b2, const float* __restrict__ b3,
    const float* __restrict__ b4,
    const float* __restrict__ f0, const float* __restrict__ f1,
    const float* __restrict__ f2, const float* __restrict__ f3,
    const float* __restrict__ f4)
{
    __shared__ float S[8][PSTRIDE];
    int warp = threadIdx.x >> 5;
    int lane = threadIdx.x & 31;
    int c = blockIdx.x * 8 + warp;

    const float* ms[5] = {m0, m1, m2, m3, m4};
    const float* bs[5] = {b0, b1, b2, b3, b4};
    const float* fs[5] = {f0, f1, f2, f3, f4};
    const int moff[5] = {0, 3, 12, 21, 30};
    const int msz[5]  = {3, 9, 9, 9, 3};
    const int uoff[5] = {0, 3, 6, 9, 12};
    const int usz[5]  = {3, 3, 3, 3, 1};

#pragma unroll
    for (int pass = 0; pass < 2; pass++) {
        int s = lane + pass * 32;
        if (s < PSTRIDE) {
            float val;
            if (s < 33) {
                int l = (s < 3) ? 0 : (s < 12) ? 1 : (s < 21) ? 2 : (s < 30) ? 3 : 4;
                val = softplus_fast(ms[l][c * msz[l] + (s - moff[l])]);
            } else if (s < 46) {
                int u = s - 33;
                int l = (u < 3) ? 0 : (u < 6) ? 1 : (u < 9) ? 2 : (u < 12) ? 3 : 4;
                val = bs[l][c * usz[l] + (u - uoff[l])];
            } else {
                int u = s - 46;
                int l = (u < 3) ? 0 : (u < 6) ? 1 : (u < 9) ? 2 : (u < 12) ? 3 : 4;
                val = fast_tanh(fs[l][c * usz[l] + (u - uoff[l])]);
            }
            d_param[c * PSTRIDE + s] = val;
            S[warp][s] = val;
        }
    }
    __syncwarp();

    if (lane == 0) {
        const float* sp = S[warp];
        const float* bb = S[warp] + 33;
        const float* tf = S[warp] + 46;

        bool gated = false;
#pragma unroll
        for (int i = 0; i < 13; i++) gated = gated || (tf[i] != 0.0f);

        float a0 = sp[0], a1 = sp[1], a2 = sp[2];
        float v0 = bb[0], v1 = bb[1], v2 = bb[2];
#pragma unroll
        for (int l = 1; l < 4; l++) {
            const float* M = sp + 3 + (l - 1) * 9;
            const float* B = bb + 3 * l;
            float na0 = M[0]*a0 + M[1]*a1 + M[2]*a2;
            float na1 = M[3]*a0 + M[4]*a1 + M[5]*a2;
            float na2 = M[6]*a0 + M[7]*a1 + M[8]*a2;
            float nv0 = M[0]*v0 + M[1]*v1 + M[2]*v2 + B[0];
            float nv1 = M[3]*v0 + M[4]*v1 + M[5]*v2 + B[1];
            float nv2 = M[6]*v0 + M[7]*v1 + M[8]*v2 + B[2];
            a0 = na0; a1 = na1; a2 = na2;
            v0 = nv0; v1 = nv1; v2 = nv2;
        }
        float a_s = sp[30]*a0 + sp[31]*a1 + sp[32]*a2;
        float b_s = sp[30]*v0 + sp[31]*v1 + sp[32]*v2 + bb[12];

        d_affine[c] = make_float4(a_s, b_s - 0.5f * a_s, gated ? 1.0f : 0.0f, b_s);
    }
    // Writes done -> allow PDL dependents to proceed.
    asm volatile("griddepcontrol.launch_dependents;" ::: "memory");
}

// -------------------------------------------------------------------------
// Generic slow logits (gated fallback only).
// -------------------------------------------------------------------------
__device__ __noinline__ float logits_slow(const float* __restrict__ P, float t)
{
    float h[3];
#pragma unroll 1
    for (int i = 0; i < 3; i++) {
        float g = fmaf(P[i], t, P[33 + i]);
        h[i] = g + P[46 + i] * tanhf(g);
    }
#pragma unroll 1
    for (int l = 1; l < 4; l++) {
        const float* M = P + 3 + (l - 1) * 9;
        float g[3];
#pragma unroll 1
        for (int r = 0; r < 3; r++) {
            float s = P[33 + 3 * l + r];
#pragma unroll 1
            for (int k = 0; k < 3; k++) s = fmaf(M[3 * r + k], h[k], s);
            g[r] = s + P[46 + 3 * l + r] * tanhf(s);
        }
        h[0] = g[0]; h[1] = g[1]; h[2] = g[2];
    }
    float o = P[33 + 12];
#pragma unroll 1
    for (int k = 0; k < 3; k++) o = fmaf(P[30 + k], h[k], o);
    return o + P[46 + 12] * tanhf(o);
}

__device__ __forceinline__ float lk_from_LU(float L, float U)
{
    float su = L + U;
    float s = (su > 0.0f) ? -1.0f : ((su < 0.0f) ? 1.0f : 0.0f);  // -sign(L+U)
    float lk = fabsf(fast_sigmoid(s * U) - fast_sigmoid(s * L));
    return fmaxf(lk, 1e-9f);
}

// -------------------------------------------------------------------------
// Hot kernel (identical body to the 62.5us/80.9%-DRAM version, plus a PDL
// wait placed AFTER the independent input loads, BEFORE reading d_affine).
// -------------------------------------------------------------------------
__global__ void __launch_bounds__(256, 6) eb_main(
    const float4* __restrict__ x4, const float4* __restrict__ n4,
    float* __restrict__ out, int n4tot)
{
    int i4 = blockIdx.x * 256 + threadIdx.x;
    float4 xv = __ldcs(x4 + i4);
    float4 nv = __ldcs(n4 + i4);

    // Block until the prep grid has flushed its writes (no-op w/o PDL).
    asm volatile("griddepcontrol.wait;" ::: "memory");

    int c = (int)((blockIdx.x * 1024u) / HW_) % CC;
    float4 A = d_affine[c];

    float4 v = make_float4(xv.x + nv.x, xv.y + nv.y, xv.z + nv.z, xv.w + nv.w);

    float4* o4 = (float4*)out;
    __stcs(o4 + i4, v);  // outputs = v

    float4 lk;
    if (A.z == 0.0f) {
        float a = A.x, bm = A.y;
        float Lx = fmaf(a, v.x, bm), Ly = fmaf(a, v.y, bm);
        float Lz = fmaf(a, v.z, bm), Lw = fmaf(a, v.w, bm);
        lk.x = lk_from_LU(Lx, Lx + a);
        lk.y = lk_from_LU(Ly, Ly + a);
        lk.z = lk_from_LU(Lz, Lz + a);
        lk.w = lk_from_LU(Lw, Lw + a);
    } else {
        const float* P = d_param + c * PSTRIDE;
        lk.x = lk_from_LU(logits_slow(P, v.x - 0.5f), logits_slow(P, v.x + 0.5f));
        lk.y = lk_from_LU(logits_slow(P, v.y - 0.5f), logits_slow(P, v.y + 0.5f));
        lk.z = lk_from_LU(logits_slow(P, v.z - 0.5f), logits_slow(P, v.z + 0.5f));
        lk.w = lk_from_LU(logits_slow(P, v.w - 0.5f), logits_slow(P, v.w + 0.5f));
    }
    __stcs(o4 + n4tot + i4, lk);  // likelihood
}

extern "C" void kernel_launch(void* const* d_in, const int* in_sizes, int n_in,
                              void* d_out, int out_size)
{
    const float* X  = (const float*)d_in[0];
    const float* NZ = (const float*)d_in[1];

    const float *m[5], *b[5], *f[5];
    if (in_sizes[3] == 3 * in_sizes[2]) {      // signature order
        for (int i = 0; i < 5; i++) {
            m[i] = (const float*)d_in[2 + i];
            b[i] = (const float*)d_in[7 + i];
            f[i] = (const float*)d_in[12 + i];
        }
    } else {                                   // dict order m,b,f interleaved
        for (int i = 0; i < 5; i++) {
            m[i] = (const float*)d_in[2 + 3 * i];
            b[i] = (const float*)d_in[3 + 3 * i];
            f[i] = (const float*)d_in[4 + 3 * i];
        }
    }

    int N = in_sizes[0];  // B*C*H*W = 28,311,552
    int blocks = N / 1024;  // 256 threads * 4 elems

    eb_prep<<<24, 256>>>(
        m[0], m[1], m[2], m[3], m[4],
        b[0], b[1], b[2], b[3], b[4],
        f[0], f[1], f[2], f[3], f[4]);

    // Launch eb_main with programmatic dependent launch so its setup and
    // independent input loads overlap eb_prep's execution. Fall back to a
    // plain serialized launch if the attribute path fails.
    cudaLaunchAttribute attr[1];
    attr[0].id = cudaLaunchAttributeProgrammaticStreamSerialization;
    attr[0].val.programmaticStreamSerializationAllowed = 1;

    cudaLaunchConfig_t cfg = {};
    cfg.gridDim  = dim3((unsigned)blocks, 1, 1);
    cfg.blockDim = dim3(256, 1, 1);
    cfg.dynamicSmemBytes = 0;
    cfg.stream = 0;
    cfg.attrs = attr;
    cfg.numAttrs = 1;

    cudaError_t e = cudaLaunchKernelEx(&cfg, eb_main,
                                       (const float4*)X, (const float4*)NZ,
                                       (float*)d_out, N / 4);
    if (e != cudaSuccess) {
        (void)cudaGetLastError();  // clear
        eb_main<<<blocks, 256>>>((const float4*)X, (const float4*)NZ,
                                 (float*)d_out, N / 4);
    }
}

// round 10
// speedup vs baseline: 1.1068x; 1.0155x over previous
#include <cuda_runtime.h>

#define CC 192
#define HW_ 9216
#define HW4 2304      // HW_/4, groups per channel
#define PSTRIDE 59    // 33 softplus(mat) + 13 bias + 13 tanh(factor)

__device__ float  d_param[CC * PSTRIDE];
__device__ float4 d_affine[CC];   // {a, b - 0.5a, gated_flag, b}

__device__ __forceinline__ float fast_sigmoid(float x) {
    float e = __expf(-x);
    return __fdividef(1.0f, 1.0f + e);
}

__device__ __forceinline__ float fast_tanh(float x) {
    float y;
    asm("tanh.approx.f32 %0, %1;" : "=f"(y) : "f"(x));
    return y;
}

__device__ __forceinline__ float softplus_fast(float x) {
    return (x > 15.0f) ? x : __logf(1.0f + __expf(x));
}

// -------------------------------------------------------------------------
// Prep: one WARP per channel (24 blocks x 8 warps). Fast intrinsics; lane 0
// composes the affine collapse logits(t)=a*t+b (exact when all tanh gates
// are zero). Signals PDL dependents after its global writes.
// -------------------------------------------------------------------------
__global__ void __launch_bounds__(256) eb_prep(
    const float* __restrict__ m0, const float* __restrict__ m1,
    const float* __restrict__ m2, const float* __restrict__ m3,
    const float* __restrict__ m4,
    const float* __restrict__ b0, const float* __restrict__ b1,
    const float* __restrict__ b2, const float* __restrict__ b3,
    const float* __restrict__ b4,
    const float* __restrict__ f0, const float* __restrict__ f1,
    const float* __restrict__ f2, const float* __restrict__ f3,
    const float* __restrict__ f4)
{
    __shared__ float S[8][PSTRIDE];
    int warp = threadIdx.x >> 5;
    int lane = threadIdx.x & 31;
    int c = blockIdx.x * 8 + warp;

    const float* ms[5] = {m0, m1, m2, m3, m4};
    const float* bs[5] = {b0, b1, b2, b3, b4};
    const float* fs[5] = {f0, f1, f2, f3, f4};
    const int moff[5] = {0, 3, 12, 21, 30};
    const int msz[5]  = {3, 9, 9, 9, 3};
    const int uoff[5] = {0, 3, 6, 9, 12};
    const int usz[5]  = {3, 3, 3, 3, 1};

#pragma unroll
    for (int pass = 0; pass < 2; pass++) {
        int s = lane + pass * 32;
        if (s < PSTRIDE) {
            float val;
            if (s < 33) {
                int l = (s < 3) ? 0 : (s < 12) ? 1 : (s < 21) ? 2 : (s < 30) ? 3 : 4;
                val = softplus_fast(ms[l][c * msz[l] + (s - moff[l])]);
            } else if (s < 46) {
                int u = s - 33;
                int l = (u < 3) ? 0 : (u < 6) ? 1 : (u < 9) ? 2 : (u < 12) ? 3 : 4;
                val = bs[l][c * usz[l] + (u - uoff[l])];
            } else {
                int u = s - 46;
                int l = (u < 3) ? 0 : (u < 6) ? 1 : (u < 9) ? 2 : (u < 12) ? 3 : 4;
                val = fast_tanh(fs[l][c * usz[l] + (u - uoff[l])]);
            }
            d_param[c * PSTRIDE + s] = val;
            S[warp][s] = val;
        }
    }
    __syncwarp();

    if (lane == 0) {
        const float* sp = S[warp];
        const float* bb = S[warp] + 33;
        const float* tf = S[warp] + 46;

        bool gated = false;
#pragma unroll
        for (int i = 0; i < 13; i++) gated = gated || (tf[i] != 0.0f);

        float a0 = sp[0], a1 = sp[1], a2 = sp[2];
        float v0 = bb[0], v1 = bb[1], v2 = bb[2];
#pragma unroll
        for (int l = 1; l < 4; l++) {
            const float* M = sp + 3 + (l - 1) * 9;
            const float* B = bb + 3 * l;
            float na0 = M[0]*a0 + M[1]*a1 + M[2]*a2;
            float na1 = M[3]*a0 + M[4]*a1 + M[5]*a2;
            float na2 = M[6]*a0 + M[7]*a1 + M[8]*a2;
            float nv0 = M[0]*v0 + M[1]*v1 + M[2]*v2 + B[0];
            float nv1 = M[3]*v0 + M[4]*v1 + M[5]*v2 + B[1];
            float nv2 = M[6]*v0 + M[7]*v1 + M[8]*v2 + B[2];
            a0 = na0; a1 = na1; a2 = na2;
            v0 = nv0; v1 = nv1; v2 = nv2;
        }
        float a_s = sp[30]*a0 + sp[31]*a1 + sp[32]*a2;
        float b_s = sp[30]*v0 + sp[31]*v1 + sp[32]*v2 + bb[12];

        d_affine[c] = make_float4(a_s, b_s - 0.5f * a_s, gated ? 1.0f : 0.0f, b_s);
    }
    asm volatile("griddepcontrol.launch_dependents;" ::: "memory");
}

// -------------------------------------------------------------------------
// Generic slow logits (gated fallback only).
// -------------------------------------------------------------------------
__device__ __noinline__ float logits_slow(const float* __restrict__ P, float t)
{
    float h[3];
#pragma unroll 1
    for (int i = 0; i < 3; i++) {
        float g = fmaf(P[i], t, P[33 + i]);
        h[i] = g + P[46 + i] * tanhf(g);
    }
#pragma unroll 1
    for (int l = 1; l < 4; l++) {
        const float* M = P + 3 + (l - 1) * 9;
        float g[3];
#pragma unroll 1
        for (int r = 0; r < 3; r++) {
            float s = P[33 + 3 * l + r];
#pragma unroll 1
            for (int k = 0; k < 3; k++) s = fmaf(M[3 * r + k], h[k], s);
            g[r] = s + P[46 + 3 * l + r] * tanhf(s);
        }
        h[0] = g[0]; h[1] = g[1]; h[2] = g[2];
    }
    float o = P[33 + 12];
#pragma unroll 1
    for (int k = 0; k < 3; k++) o = fmaf(P[30 + k], h[k], o);
    return o + P[46 + 12] * tanhf(o);
}

__device__ __forceinline__ float lk_from_LU(float L, float U)
{
    float su = L + U;
    float s = (su > 0.0f) ? -1.0f : ((su < 0.0f) ? 1.0f : 0.0f);  // -sign(L+U)
    float lk = fabsf(fast_sigmoid(s * U) - fast_sigmoid(s * L));
    return fmaxf(lk, 1e-9f);
}

__device__ __forceinline__ float4 lk_group(float4 A, float4 v, unsigned c)
{
    float4 lk;
    if (A.z == 0.0f) {
        float a = A.x, bm = A.y;
        float Lx = fmaf(a, v.x, bm), Ly = fmaf(a, v.y, bm);
        float Lz = fmaf(a, v.z, bm), Lw = fmaf(a, v.w, bm);
        lk.x = lk_from_LU(Lx, Lx + a);
        lk.y = lk_from_LU(Ly, Ly + a);
        lk.z = lk_from_LU(Lz, Lz + a);
        lk.w = lk_from_LU(Lw, Lw + a);
    } else {
        const float* P = d_param + c * PSTRIDE;
        lk.x = lk_from_LU(logits_slow(P, v.x - 0.5f), logits_slow(P, v.x + 0.5f));
        lk.y = lk_from_LU(logits_slow(P, v.y - 0.5f), logits_slow(P, v.y + 0.5f));
        lk.z = lk_from_LU(logits_slow(P, v.z - 0.5f), logits_slow(P, v.z + 0.5f));
        lk.w = lk_from_LU(logits_slow(P, v.w - 0.5f), logits_slow(P, v.w + 0.5f));
    }
    return lk;
}

// -------------------------------------------------------------------------
// Hot kernel: 2 float4-groups per thread (8 elems) -> 4 outstanding 16B
// loads per thread for deeper MLP / higher DRAM utilization. Channel is
// computed per group (g/2304 % 192); d_affine is a hot 3KB cached table.
// PDL wait sits after the independent input loads.
// -------------------------------------------------------------------------
__global__ void __launch_bounds__(256, 6) eb_main(
    const float4* __restrict__ x4, const float4* __restrict__ n4,
    float* __restrict__ out, int n4tot)
{
    unsigned g0 = blockIdx.x * 512u + threadIdx.x;
    unsigned g1 = g0 + 256u;

    float4 xv0 = __ldcs(x4 + g0);
    float4 nv0 = __ldcs(n4 + g0);
    float4 xv1 = __ldcs(x4 + g1);
    float4 nv1 = __ldcs(n4 + g1);

    asm volatile("griddepcontrol.wait;" ::: "memory");

    unsigned c0 = (g0 / HW4) % CC;
    unsigned c1 = (g1 / HW4) % CC;
    float4 A0 = d_affine[c0];
    float4 A1 = d_affine[c1];

    float4 v0 = make_float4(xv0.x + nv0.x, xv0.y + nv0.y, xv0.z + nv0.z, xv0.w + nv0.w);
    float4 v1 = make_float4(xv1.x + nv1.x, xv1.y + nv1.y, xv1.z + nv1.z, xv1.w + nv1.w);

    float4* o4 = (float4*)out;
    __stcs(o4 + g0, v0);
    __stcs(o4 + g1, v1);

    float4 lk0 = lk_group(A0, v0, c0);
    float4 lk1 = lk_group(A1, v1, c1);

    __stcs(o4 + n4tot + g0, lk0);
    __stcs(o4 + n4tot + g1, lk1);
}

extern "C" void kernel_launch(void* const* d_in, const int* in_sizes, int n_in,
                              void* d_out, int out_size)
{
    const float* X  = (const float*)d_in[0];
    const float* NZ = (const float*)d_in[1];

    const float *m[5], *b[5], *f[5];
    if (in_sizes[3] == 3 * in_sizes[2]) {      // signature order
        for (int i = 0; i < 5; i++) {
            m[i] = (const float*)d_in[2 + i];
            b[i] = (const float*)d_in[7 + i];
            f[i] = (const float*)d_in[12 + i];
        }
    } else {                                   // dict order m,b,f interleaved
        for (int i = 0; i < 5; i++) {
            m[i] = (const float*)d_in[2 + 3 * i];
            b[i] = (const float*)d_in[3 + 3 * i];
            f[i] = (const float*)d_in[4 + 3 * i];
        }
    }

    int N = in_sizes[0];  // B*C*H*W = 28,311,552
    int blocks = N / 2048;  // 256 threads * 8 elems

    eb_prep<<<24, 256>>>(
        m[0], m[1], m[2], m[3], m[4],
        b[0], b[1], b[2], b[3], b[4],
        f[0], f[1], f[2], f[3], f[4]);

    cudaLaunchAttribute attr[1];
    attr[0].id = cudaLaunchAttributeProgrammaticStreamSerialization;
    attr[0].val.programmaticStreamSerializationAllowed = 1;

    cudaLaunchConfig_t cfg = {};
    cfg.gridDim  = dim3((unsigned)blocks, 1, 1);
    cfg.blockDim = dim3(256, 1, 1);
    cfg.dynamicSmemBytes = 0;
    cfg.stream = 0;
    cfg.attrs = attr;
    cfg.numAttrs = 1;

    cudaError_t e = cudaLaunchKernelEx(&cfg, eb_main,
                                       (const float4*)X, (const float4*)NZ,
                                       (float*)d_out, N / 4);
    if (e != cudaSuccess) {
        (void)cudaGetLastError();
        eb_main<<<blocks, 256>>>((const float4*)X, (const float4*)NZ,
                                 (float*)d_out, N / 4);
    }
}